// round 2
// baseline (speedup 1.0000x reference)
#include <cuda_runtime.h>
#include <cstdint>

#define NQ      8
#define NLAYERS 4
#define DIN     1024
#define DOUT    1024

// Precomputed combined RZ(phi)*RX(theta) 2x2 complex coefficients for the 32
// layer gates: [l*8+i][8] = {u00r,u00i, u01r,u01i, u10r,u10i, u11r,u11i}
__device__ float g_ucoef[NLAYERS * NQ * 8];

__global__ void prep_kernel(const float* __restrict__ qw) {
    int t = threadIdx.x;
    if (t < NLAYERS * NQ) {
        int l = t >> 3, i = t & 7;
        float th = qw[l * 16 + i];        // weights[l][0][i] (RX)
        float ph = qw[l * 16 + 8 + i];    // weights[l][1][i] (RZ)
        float s, c, sp, cp;
        sincosf(0.5f * th, &s, &c);
        sincosf(0.5f * ph, &sp, &cp);
        float* u = &g_ucoef[t * 8];
        // U = diag(e^{-i ph/2}, e^{i ph/2}) * [[c, -i s],[-i s, c]]
        u[0] =  c * cp;  u[1] = -c * sp;   // u00
        u[2] = -s * sp;  u[3] = -s * cp;   // u01
        u[4] =  s * sp;  u[5] = -s * cp;   // u10
        u[6] =  c * cp;  u[7] =  c * sp;   // u11
    }
}

#define SWAP(a, b) { float _t = a; a = b; b = _t; }

// 4 rows per warp: sub = lane>>3 selects the row, li = lane&7.
// Amplitude index k = li*32 + r. Wire i uses bit (7-i) of k:
//   wires 0,1,2 -> lane(li) bits 2,1,0 ; wires 3..7 -> r bits 4,3,2,1,0.
__global__ __launch_bounds__(128, 4)
void qasa_kernel(const float* __restrict__ x,
                 const float* __restrict__ Win,
                 const float* __restrict__ bin,
                 const float* __restrict__ Wout,
                 const float* __restrict__ bout,
                 float* __restrict__ out)
{
    const int lane = threadIdx.x & 31;
    const int warp = threadIdx.x >> 5;
    const int li   = lane & 7;
    const int sub  = lane >> 3;
    const int row  = (blockIdx.x * 4 + warp) * 4 + sub;

    // ---------------- 1) angles = x[row] @ Win^T + bin ----------------
    float acc[NQ];
#pragma unroll
    for (int q = 0; q < NQ; q++) acc[q] = 0.f;

    const float4* x4 = reinterpret_cast<const float4*>(x + (size_t)row * DIN);
    const float4* w4 = reinterpret_cast<const float4*>(Win);
#pragma unroll
    for (int j = 0; j < 32; j++) {
        float4 xv = __ldcs(&x4[li + 8 * j]);
#pragma unroll
        for (int q = 0; q < NQ; q++) {
            float4 wv = __ldg(&w4[q * 256 + li + 8 * j]);   // broadcast over sub groups
            acc[q] += xv.x * wv.x + xv.y * wv.y + xv.z * wv.z + xv.w * wv.w;
        }
    }
#pragma unroll
    for (int off = 4; off; off >>= 1)
#pragma unroll
        for (int q = 0; q < NQ; q++)
            acc[q] += __shfl_xor_sync(0xffffffffu, acc[q], off);

    // C = cos(theta/2), S = sin(theta/2) for each wire
    float C[NQ], S[NQ];
#pragma unroll
    for (int q = 0; q < NQ; q++) {
        float h = 0.5f * (acc[q] + __ldg(&bin[q]));
        __sincosf(h, &S[q], &C[q]);
    }

    // ---------------- 2) initial product state -----------------------
    // After RX(th)RZ(th): qubit vector q0=(C^2, -S*C), q1=(S^2, -S*C)
    float ar[32], ai[32];
    {
        float prr = 1.f, pri = 0.f;
#pragma unroll
        for (int w = 0; w < 3; w++) {           // lane wires
            int b = (li >> (2 - w)) & 1;
            float qr = b ? S[w] * S[w] : C[w] * C[w];
            float qi = -S[w] * C[w];
            float nr = prr * qr - pri * qi;
            pri = prr * qi + pri * qr;
            prr = nr;
        }
        ar[0] = prr; ai[0] = pri;
        int cnt = 1;
#pragma unroll
        for (int w = 7; w >= 3; w--) {          // local wires, doubling
            float q0r = C[w] * C[w], q1r = S[w] * S[w], qi = -S[w] * C[w];
#pragma unroll
            for (int j = 0; j < 16; j++) {
                if (j < cnt) {
                    float br = ar[j], bi = ai[j];
                    ar[j + cnt] = br * q1r - bi * qi;
                    ai[j + cnt] = br * qi + bi * q1r;
                    ar[j] = br * q0r - bi * qi;
                    ai[j] = br * qi + bi * q0r;
                }
            }
            cnt <<= 1;
        }
    }

    // ---------------- 3) 4 entangling layers --------------------------
#pragma unroll
    for (int l = 0; l < NLAYERS; l++) {
#pragma unroll
        for (int i = 0; i < NQ; i++) {
            const float4* u4 = reinterpret_cast<const float4*>(&g_ucoef[(l * NQ + i) * 8]);
            float4 ua = __ldg(u4 + 0);   // u00r,u00i,u01r,u01i
            float4 ub = __ldg(u4 + 1);   // u10r,u10i,u11r,u11i
            if (i < 3) {
                // gate on lane bit L = 2-i
                const int L = 2 - i;
                bool hi = (li >> L) & 1;
                float dr  = hi ? ub.z : ua.x, di = hi ? ub.w : ua.y;
                float orr = hi ? ub.x : ua.z, oi = hi ? ub.y : ua.w;
#pragma unroll
                for (int r = 0; r < 32; r++) {
                    float pr = __shfl_xor_sync(0xffffffffu, ar[r], 1 << L);
                    float pi = __shfl_xor_sync(0xffffffffu, ai[r], 1 << L);
                    float mr = ar[r], mi = ai[r];
                    ar[r] = dr * mr - di * mi + orr * pr - oi * pi;
                    ai[r] = dr * mi + di * mr + orr * pi + oi * pr;
                }
            } else {
                // gate on local r-bit (7-i)
                const int m = 1 << (7 - i);
#pragma unroll
                for (int r = 0; r < 32; r++) {
                    if (!(r & m)) {
                        int r1 = r | m;
                        float a_r = ar[r],  a_i = ai[r];
                        float b_r = ar[r1], b_i = ai[r1];
                        ar[r]  = ua.x * a_r - ua.y * a_i + ua.z * b_r - ua.w * b_i;
                        ai[r]  = ua.x * a_i + ua.y * a_r + ua.z * b_i + ua.w * b_r;
                        ar[r1] = ub.x * a_r - ub.y * a_i + ub.z * b_r - ub.w * b_i;
                        ai[r1] = ub.x * a_i + ub.y * a_r + ub.z * b_i + ub.w * b_r;
                    }
                }
            }
        }
        { // CNOT(0,1): control lane bit2, target lane bit1
            bool ctrl = (li >> 2) & 1;
#pragma unroll
            for (int r = 0; r < 32; r++) {
                float pr = __shfl_xor_sync(0xffffffffu, ar[r], 2);
                float pi = __shfl_xor_sync(0xffffffffu, ai[r], 2);
                ar[r] = ctrl ? pr : ar[r];
                ai[r] = ctrl ? pi : ai[r];
            }
        }
        { // CNOT(1,2): control lane bit1, target lane bit0
            bool ctrl = (li >> 1) & 1;
#pragma unroll
            for (int r = 0; r < 32; r++) {
                float pr = __shfl_xor_sync(0xffffffffu, ar[r], 1);
                float pi = __shfl_xor_sync(0xffffffffu, ai[r], 1);
                ar[r] = ctrl ? pr : ar[r];
                ai[r] = ctrl ? pi : ai[r];
            }
        }
        { // CNOT(2,3): control lane bit0, target r bit4 (swap r <-> r+16)
            bool ctrl = li & 1;
#pragma unroll
            for (int j = 0; j < 16; j++) {
                float t0 = ar[j], t1 = ar[j + 16];
                ar[j] = ctrl ? t1 : t0; ar[j + 16] = ctrl ? t0 : t1;
                float s0 = ai[j], s1 = ai[j + 16];
                ai[j] = ctrl ? s1 : s0; ai[j + 16] = ctrl ? s0 : s1;
            }
        }
        { // CNOT(3,4): ctrl r bit4 -> flip bit3: swap (16..23)<->(24..31)  [rename]
#pragma unroll
            for (int j = 0; j < 8; j++) {
                SWAP(ar[16 + j], ar[24 + j]); SWAP(ai[16 + j], ai[24 + j]);
            }
        }
        { // CNOT(4,5): ctrl r bit3 -> flip bit2  [rename]
#pragma unroll
            for (int j = 0; j < 4; j++) {
                SWAP(ar[8 + j],  ar[12 + j]); SWAP(ai[8 + j],  ai[12 + j]);
                SWAP(ar[24 + j], ar[28 + j]); SWAP(ai[24 + j], ai[28 + j]);
            }
        }
        { // CNOT(5,6): ctrl r bit2 -> flip bit1  [rename]
#pragma unroll
            for (int b = 0; b < 4; b++) {
                int o = b * 8;
                SWAP(ar[o + 4], ar[o + 6]); SWAP(ai[o + 4], ai[o + 6]);
                SWAP(ar[o + 5], ar[o + 7]); SWAP(ai[o + 5], ai[o + 7]);
            }
        }
        { // CNOT(6,7): ctrl r bit1 -> flip bit0  [rename]
#pragma unroll
            for (int b = 0; b < 8; b++) {
                int o = b * 4;
                SWAP(ar[o + 2], ar[o + 3]); SWAP(ai[o + 2], ai[o + 3]);
            }
        }
    }

    // ---------------- 4) expectation values <Z_i> ---------------------
    float p[32];
#pragma unroll
    for (int r = 0; r < 32; r++) p[r] = ar[r] * ar[r] + ai[r] * ai[r];
    float ptot = 0.f;
#pragma unroll
    for (int r = 0; r < 32; r++) ptot += p[r];

    float ev[NQ];
#pragma unroll
    for (int i = 0; i < 3; i++)
        ev[i] = ((li >> (2 - i)) & 1) ? -ptot : ptot;
#pragma unroll
    for (int i = 3; i < 8; i++) {
        float s = 0.f;
#pragma unroll
        for (int r = 0; r < 32; r++)
            s += ((r >> (7 - i)) & 1) ? -p[r] : p[r];
        ev[i] = s;
    }
#pragma unroll
    for (int off = 4; off; off >>= 1)
#pragma unroll
        for (int i = 0; i < NQ; i++)
            ev[i] += __shfl_xor_sync(0xffffffffu, ev[i], off);

    // ---------------- 5) out[row] = ev @ Wout^T + bout ----------------
    const float4* bo4 = reinterpret_cast<const float4*>(bout);
    const float4* wo4 = reinterpret_cast<const float4*>(Wout);   // [DOUT][2] float4
    float4* out4 = reinterpret_cast<float4*>(out) + (size_t)row * (DOUT / 4);
#pragma unroll
    for (int j = 0; j < 32; j++) {
        int c4 = li + 8 * j;          // float4 column index (broadcast over sub)
        float4 o = __ldg(&bo4[c4]);
        int obase = c4 * 4;
        float* op = &o.x;
#pragma unroll
        for (int oo = 0; oo < 4; oo++) {
            float4 wa = __ldg(&wo4[(obase + oo) * 2 + 0]);
            float4 wb = __ldg(&wo4[(obase + oo) * 2 + 1]);
            op[oo] += ev[0] * wa.x + ev[1] * wa.y + ev[2] * wa.z + ev[3] * wa.w
                    + ev[4] * wb.x + ev[5] * wb.y + ev[6] * wb.z + ev[7] * wb.w;
        }
        out4[c4] = o;
    }
}

extern "C" void kernel_launch(void* const* d_in, const int* in_sizes, int n_in,
                              void* d_out, int out_size) {
    const float* x    = (const float*)d_in[0];
    const float* Win  = (const float*)d_in[1];
    const float* bin  = (const float*)d_in[2];
    const float* qw   = (const float*)d_in[3];
    const float* Wout = (const float*)d_in[4];
    const float* bout = (const float*)d_in[5];
    float* out = (float*)d_out;

    int B = in_sizes[0] / DIN;        // 8192
    prep_kernel<<<1, 32>>>(qw);
    qasa_kernel<<<B / 16, 128>>>(x, Win, bin, Wout, bout, out);
}

// round 3
// speedup vs baseline: 2.1881x; 2.1881x over previous
#include <cuda_runtime.h>
#include <cstdint>

#define NQ      8
#define NLAYERS 4
#define DIN     1024
#define DOUT    1024
#define BMAX    8192

using ull = unsigned long long;

// ---------------- packed f32x2 helpers (Blackwell dual-FP32) ----------------
__device__ __forceinline__ ull pk(float x, float y) {
    ull r; asm("mov.b64 %0,{%1,%2};" : "=l"(r) : "f"(x), "f"(y)); return r;
}
__device__ __forceinline__ void up2(ull a, float& x, float& y) {
    asm("mov.b64 {%0,%1},%2;" : "=f"(x), "=f"(y) : "l"(a));
}
__device__ __forceinline__ ull dup2(float x) { return pk(x, x); }
__device__ __forceinline__ ull fma2(ull a, ull b, ull c) {
    ull d; asm("fma.rn.f32x2 %0,%1,%2,%3;" : "=l"(d) : "l"(a), "l"(b), "l"(c)); return d;
}
__device__ __forceinline__ ull mul2(ull a, ull b) {
    ull d; asm("mul.rn.f32x2 %0,%1,%2;" : "=l"(d) : "l"(a), "l"(b)); return d;
}
__device__ __forceinline__ ull swp(ull a) { float x, y; up2(a, x, y); return pk(y, x); }
__device__ __forceinline__ ull shflx(ull a, int m) {
    float x, y; up2(a, x, y);
    x = __shfl_xor_sync(0xffffffffu, x, m);
    y = __shfl_xor_sync(0xffffffffu, y, m);
    return pk(x, y);
}

// ---------------- device buffers / gate coefficients ----------------
__device__ float g_ucoef[NLAYERS * NQ * 8];
__device__ float2 g_cs[BMAX * NQ];   // (cos(h), sin(h)) per row per wire
__device__ float  g_ev[BMAX * NQ];   // <Z_i> per row

__global__ void prep_kernel(const float* __restrict__ qw) {
    int t = threadIdx.x;
    if (t < NLAYERS * NQ) {
        int l = t >> 3, i = t & 7;
        float th = qw[l * 16 + i];        // weights[l][0][i] (RX)
        float ph = qw[l * 16 + 8 + i];    // weights[l][1][i] (RZ)
        float s, c, sp, cp;
        sincosf(0.5f * th, &s, &c);
        sincosf(0.5f * ph, &sp, &cp);
        float* u = &g_ucoef[t * 8];
        u[0] =  c * cp;  u[1] = -c * sp;   // u00
        u[2] = -s * sp;  u[3] = -s * cp;   // u01
        u[4] =  s * sp;  u[5] = -s * cp;   // u10
        u[6] =  c * cp;  u[7] =  c * sp;   // u11
    }
}

// ================= K1: angles = x @ Win^T + bin ; store (cos,sin) =========
// 4 warps/block, 4 rows/warp: weight loads amortized over 4 rows.
__global__ __launch_bounds__(128)
void k1_angles(const float* __restrict__ x,
               const float* __restrict__ Win,
               const float* __restrict__ bin)
{
    const int lane = threadIdx.x & 31;
    const int warp = threadIdx.x >> 5;
    const int row0 = (blockIdx.x * 4 + warp) * 4;

    float acc[4][NQ];
#pragma unroll
    for (int r = 0; r < 4; r++)
#pragma unroll
        for (int q = 0; q < NQ; q++) acc[r][q] = 0.f;

    const float4* w4 = reinterpret_cast<const float4*>(Win);
    const float4* xr[4];
#pragma unroll
    for (int r = 0; r < 4; r++)
        xr[r] = reinterpret_cast<const float4*>(x + (size_t)(row0 + r) * DIN);

#pragma unroll
    for (int j = 0; j < 8; j++) {
        float4 wv[NQ];
#pragma unroll
        for (int q = 0; q < NQ; q++)
            wv[q] = __ldg(&w4[q * 256 + lane + 32 * j]);
#pragma unroll
        for (int r = 0; r < 4; r++) {
            float4 xv = __ldcs(&xr[r][lane + 32 * j]);
#pragma unroll
            for (int q = 0; q < NQ; q++)
                acc[r][q] += xv.x * wv[q].x + xv.y * wv[q].y
                           + xv.z * wv[q].z + xv.w * wv[q].w;
        }
    }
#pragma unroll
    for (int off = 16; off; off >>= 1)
#pragma unroll
        for (int r = 0; r < 4; r++)
#pragma unroll
            for (int q = 0; q < NQ; q++)
                acc[r][q] += __shfl_xor_sync(0xffffffffu, acc[r][q], off);

    // one (row, wire) task per lane
    int r = lane >> 3, q = lane & 7;
    float h = 0.5f * (acc[r][q] + __ldg(&bin[q]));
    float s, c;
    __sincosf(h, &s, &c);
    g_cs[(size_t)(row0 + r) * NQ + q] = make_float2(c, s);
}

// ================= K2: quantum circuit (pure register/shuffle) ============
// One warp per row. Amp index k = lane*8 + r. Wires 0..4 -> lane bits 4..0,
// wires 5..7 -> r bits 2..0. State packed as f32x2 pairs: Ar[j] = (a_{2j}, a_{2j+1}).
struct GP {     // packed 2x2 complex gate coefficients (+negatives)
    ull r00, i00, ni00, r01, i01, ni01, r10, i10, ni10, r11, i11, ni11;
};

__device__ __forceinline__ void gate_pair(ull& Ar0, ull& Ai0, ull& Ar1, ull& Ai1,
                                          const GP& g)
{
    ull nr0 = fma2(g.ni01, Ai1, fma2(g.r01, Ar1, fma2(g.ni00, Ai0, mul2(g.r00, Ar0))));
    ull ni0 = fma2(g.i01,  Ar1, fma2(g.r01, Ai1, fma2(g.i00,  Ar0, mul2(g.r00, Ai0))));
    ull nr1 = fma2(g.ni11, Ai1, fma2(g.r11, Ar1, fma2(g.ni10, Ai0, mul2(g.r10, Ar0))));
    ull ni1 = fma2(g.i11,  Ar1, fma2(g.r11, Ai1, fma2(g.i10,  Ar0, mul2(g.r10, Ai0))));
    Ar0 = nr0; Ai0 = ni0; Ar1 = nr1; Ai1 = ni1;
}

__global__ __launch_bounds__(256)
void k2_circuit()
{
    const int lane = threadIdx.x & 31;
    const int warp = threadIdx.x >> 5;
    const int row  = blockIdx.x * 8 + warp;

    // load per-row (cos,sin) for each wire (uniform across warp)
    float C[NQ], S[NQ];
    {
        const float4* cs4 = reinterpret_cast<const float4*>(&g_cs[(size_t)row * NQ]);
#pragma unroll
        for (int j = 0; j < 4; j++) {
            float4 v = __ldg(&cs4[j]);
            C[2 * j] = v.x; S[2 * j] = v.y; C[2 * j + 1] = v.z; S[2 * j + 1] = v.w;
        }
    }

    // initial product state (scalar build, then pack)
    float ar[8], ai[8];
    {
        float prr = 1.f, pri = 0.f;
#pragma unroll
        for (int w = 0; w < 5; w++) {
            int b = (lane >> (4 - w)) & 1;
            float qr = b ? S[w] * S[w] : C[w] * C[w];
            float qi = -S[w] * C[w];
            float nr = prr * qr - pri * qi;
            pri = prr * qi + pri * qr;
            prr = nr;
        }
#pragma unroll
        for (int r = 0; r < 8; r++) {
            float lr = prr, li = pri;
#pragma unroll
            for (int w = 5; w < 8; w++) {
                int b = (r >> (7 - w)) & 1;
                float qr = b ? S[w] * S[w] : C[w] * C[w];
                float qi = -S[w] * C[w];
                float nr = lr * qr - li * qi;
                li = lr * qi + li * qr;
                lr = nr;
            }
            ar[r] = lr; ai[r] = li;
        }
    }
    ull Ar[4], Ai[4];
#pragma unroll
    for (int j = 0; j < 4; j++) { Ar[j] = pk(ar[2 * j], ar[2 * j + 1]); Ai[j] = pk(ai[2 * j], ai[2 * j + 1]); }

    // 4 entangling layers
#pragma unroll
    for (int l = 0; l < NLAYERS; l++) {
#pragma unroll
        for (int i = 0; i < NQ; i++) {
            const float4* u4 = reinterpret_cast<const float4*>(&g_ucoef[(l * NQ + i) * 8]);
            float4 ua = __ldg(u4 + 0);   // u00r,u00i,u01r,u01i
            float4 ub = __ldg(u4 + 1);   // u10r,u10i,u11r,u11i
            if (i < 3 || i == 3 || i == 4) { }
            if (i < 5) {
                // lane-bit gate, bit L = 4-i
                const int L = 4 - i;
                const int msk = 1 << L;
                bool hi = (lane >> L) & 1;
                float dr  = hi ? ub.z : ua.x, di = hi ? ub.w : ua.y;
                float orr = hi ? ub.x : ua.z, oi = hi ? ub.y : ua.w;
                ull drp = dup2(dr), dip = dup2(di), ndip = dup2(-di);
                ull orp = dup2(orr), oip = dup2(oi), noip = dup2(-oi);
#pragma unroll
                for (int j = 0; j < 4; j++) {
                    ull Pr = shflx(Ar[j], msk);
                    ull Pi = shflx(Ai[j], msk);
                    ull nr = fma2(noip, Pi, fma2(orp, Pr, fma2(ndip, Ai[j], mul2(drp, Ar[j]))));
                    ull ni = fma2(oip,  Pr, fma2(orp, Pi, fma2(dip,  Ar[j], mul2(drp, Ai[j]))));
                    Ar[j] = nr; Ai[j] = ni;
                }
            } else if (i == 5) {
                // local bit2 (m=4): packed groups (0,2) and (1,3)
                GP g = { dup2(ua.x), dup2(ua.y), dup2(-ua.y),
                         dup2(ua.z), dup2(ua.w), dup2(-ua.w),
                         dup2(ub.x), dup2(ub.y), dup2(-ub.y),
                         dup2(ub.z), dup2(ub.w), dup2(-ub.w) };
                gate_pair(Ar[0], Ai[0], Ar[2], Ai[2], g);
                gate_pair(Ar[1], Ai[1], Ar[3], Ai[3], g);
            } else if (i == 6) {
                // local bit1 (m=2): packed groups (0,1) and (2,3)
                GP g = { dup2(ua.x), dup2(ua.y), dup2(-ua.y),
                         dup2(ua.z), dup2(ua.w), dup2(-ua.w),
                         dup2(ub.x), dup2(ub.y), dup2(-ub.y),
                         dup2(ub.z), dup2(ub.w), dup2(-ub.w) };
                gate_pair(Ar[0], Ai[0], Ar[1], Ai[1], g);
                gate_pair(Ar[2], Ai[2], Ar[3], Ai[3], g);
            } else {
                // local bit0 (m=1): intra-register pair via half-swap + coef pairs
                ull K1r = pk(ua.x, ub.z), K1i = pk(ua.y, ub.w), nK1i = pk(-ua.y, -ub.w);
                ull K2r = pk(ua.z, ub.x), K2i = pk(ua.w, ub.y), nK2i = pk(-ua.w, -ub.y);
#pragma unroll
                for (int j = 0; j < 4; j++) {
                    ull Sr = swp(Ar[j]), Si = swp(Ai[j]);
                    ull nr = fma2(nK2i, Si, fma2(K2r, Sr, fma2(nK1i, Ai[j], mul2(K1r, Ar[j]))));
                    ull ni = fma2(K2i,  Sr, fma2(K2r, Si, fma2(K1i,  Ar[j], mul2(K1r, Ai[j]))));
                    Ar[j] = nr; Ai[j] = ni;
                }
            }
        }
        // CNOT chain (0,1)(1,2)(2,3)(3,4): control lane bit cl, target bit cl-1
#pragma unroll
        for (int cl = 4; cl >= 1; cl--) {
            bool ctrl = (lane >> cl) & 1;
            const int tmask = 1 << (cl - 1);
#pragma unroll
            for (int j = 0; j < 4; j++) {
                ull Pr = shflx(Ar[j], tmask);
                ull Pi = shflx(Ai[j], tmask);
                Ar[j] = ctrl ? Pr : Ar[j];
                Ai[j] = ctrl ? Pi : Ai[j];
            }
        }
        { // CNOT(4,5): control lane bit0, target local bit2: swap packed 0<->2, 1<->3
            bool ctrl = lane & 1;
            ull t;
            t = Ar[0]; Ar[0] = ctrl ? Ar[2] : Ar[0]; Ar[2] = ctrl ? t : Ar[2];
            t = Ar[1]; Ar[1] = ctrl ? Ar[3] : Ar[1]; Ar[3] = ctrl ? t : Ar[3];
            t = Ai[0]; Ai[0] = ctrl ? Ai[2] : Ai[0]; Ai[2] = ctrl ? t : Ai[2];
            t = Ai[1]; Ai[1] = ctrl ? Ai[3] : Ai[1]; Ai[3] = ctrl ? t : Ai[3];
        }
        { // CNOT(5,6): swap amps (4,6),(5,7) -> swap packed regs 2<->3 (rename)
            ull t;
            t = Ar[2]; Ar[2] = Ar[3]; Ar[3] = t;
            t = Ai[2]; Ai[2] = Ai[3]; Ai[3] = t;
        }
        { // CNOT(6,7): swap amps (2,3),(6,7) -> half-swap packed regs 1 and 3
            Ar[1] = swp(Ar[1]); Ar[3] = swp(Ar[3]);
            Ai[1] = swp(Ai[1]); Ai[3] = swp(Ai[3]);
        }
    }

    // expectation values
    ull P[4];
#pragma unroll
    for (int j = 0; j < 4; j++) P[j] = fma2(Ai[j], Ai[j], mul2(Ar[j], Ar[j]));
    float p[8];
#pragma unroll
    for (int j = 0; j < 4; j++) up2(P[j], p[2 * j], p[2 * j + 1]);

    float ptot = ((p[0] + p[1]) + (p[2] + p[3])) + ((p[4] + p[5]) + (p[6] + p[7]));

    float ev[NQ];
#pragma unroll
    for (int i = 0; i < 5; i++)
        ev[i] = ((lane >> (4 - i)) & 1) ? -ptot : ptot;
    ev[5] = ((p[0] + p[1]) + (p[2] + p[3])) - ((p[4] + p[5]) + (p[6] + p[7]));
    ev[6] = ((p[0] + p[1]) - (p[2] + p[3])) + ((p[4] + p[5]) - (p[6] + p[7]));
    ev[7] = ((p[0] - p[1]) + (p[2] - p[3])) + ((p[4] - p[5]) + (p[6] - p[7]));

#pragma unroll
    for (int off = 16; off; off >>= 1)
#pragma unroll
        for (int i = 0; i < NQ; i++)
            ev[i] += __shfl_xor_sync(0xffffffffu, ev[i], off);

    if (lane < NQ)
        g_ev[(size_t)row * NQ + lane] = ev[lane];
}

// ================= K3: out = ev @ Wout^T + bout ===========================
// Block 256 = 8 warps; warp w owns cols [w*128, w*128+128); lane owns 4 cols.
// Weights held in registers across 32 rows.
__global__ __launch_bounds__(256)
void k3_out(const float* __restrict__ Wout,
            const float* __restrict__ bout,
            float* __restrict__ out)
{
    const int lane = threadIdx.x & 31;
    const int warp = threadIdx.x >> 5;
    const int c0   = warp * 128 + lane * 4;     // first of 4 cols
    const int row0 = blockIdx.x * 32;

    const float4* wo4 = reinterpret_cast<const float4*>(Wout);  // [DOUT][2]
    float4 wa[4], wb[4];
#pragma unroll
    for (int k = 0; k < 4; k++) {
        wa[k] = __ldg(&wo4[(c0 + k) * 2 + 0]);
        wb[k] = __ldg(&wo4[(c0 + k) * 2 + 1]);
    }
    float4 bo = __ldg(&reinterpret_cast<const float4*>(bout)[c0 >> 2]);

#pragma unroll 4
    for (int r = 0; r < 32; r++) {
        int row = row0 + r;
        const float4* e4 = reinterpret_cast<const float4*>(&g_ev[(size_t)row * NQ]);
        float4 ea = __ldg(e4 + 0);
        float4 eb = __ldg(e4 + 1);
        float4 o;
        float* op = &o.x;
#pragma unroll
        for (int k = 0; k < 4; k++) {
            op[k] = (k == 0 ? bo.x : k == 1 ? bo.y : k == 2 ? bo.z : bo.w)
                  + ea.x * wa[k].x + ea.y * wa[k].y + ea.z * wa[k].z + ea.w * wa[k].w
                  + eb.x * wb[k].x + eb.y * wb[k].y + eb.z * wb[k].z + eb.w * wb[k].w;
        }
        reinterpret_cast<float4*>(out + (size_t)row * DOUT)[c0 >> 2] = o;
    }
}

extern "C" void kernel_launch(void* const* d_in, const int* in_sizes, int n_in,
                              void* d_out, int out_size) {
    const float* x    = (const float*)d_in[0];
    const float* Win  = (const float*)d_in[1];
    const float* bin  = (const float*)d_in[2];
    const float* qw   = (const float*)d_in[3];
    const float* Wout = (const float*)d_in[4];
    const float* bout = (const float*)d_in[5];
    float* out = (float*)d_out;

    int B = in_sizes[0] / DIN;            // 8192
    prep_kernel<<<1, 32>>>(qw);
    k1_angles<<<B / 16, 128>>>(x, Win, bin);
    k2_circuit<<<B / 8, 256>>>();
    k3_out<<<B / 32, 256>>>(Wout, bout, out);
}

// round 4
// speedup vs baseline: 2.2531x; 1.0297x over previous
#include <cuda_runtime.h>
#include <cstdint>

#define NQ      8
#define NLAYERS 4
#define DIN     1024
#define DOUT    1024
#define BMAX    8192

using ull = unsigned long long;

// ---------------- packed f32x2 helpers (Blackwell dual-FP32) ----------------
__device__ __forceinline__ ull pk(float x, float y) {
    ull r; asm("mov.b64 %0,{%1,%2};" : "=l"(r) : "f"(x), "f"(y)); return r;
}
__device__ __forceinline__ void up2(ull a, float& x, float& y) {
    asm("mov.b64 {%0,%1},%2;" : "=f"(x), "=f"(y) : "l"(a));
}
__device__ __forceinline__ ull dup2(float x) { return pk(x, x); }
__device__ __forceinline__ ull fma2(ull a, ull b, ull c) {
    ull d; asm("fma.rn.f32x2 %0,%1,%2,%3;" : "=l"(d) : "l"(a), "l"(b), "l"(c)); return d;
}
__device__ __forceinline__ ull mul2(ull a, ull b) {
    ull d; asm("mul.rn.f32x2 %0,%1,%2;" : "=l"(d) : "l"(a), "l"(b)); return d;
}
__device__ __forceinline__ ull swp(ull a) { float x, y; up2(a, x, y); return pk(y, x); }
__device__ __forceinline__ ull shflx(ull a, int m) {
    float x, y; up2(a, x, y);
    x = __shfl_xor_sync(0xffffffffu, x, m);
    y = __shfl_xor_sync(0xffffffffu, y, m);
    return pk(x, y);
}

// ---------------- device buffers / gate coefficients ----------------
__device__ float  g_ucoef[NLAYERS * NQ * 8];
__device__ float2 g_cs[BMAX * NQ];   // (cos(h), sin(h)) per row per wire
__device__ float  g_ev[BMAX * NQ];   // <Z_i> per row

// ================= K1: angles = x @ Win^T + bin ; store (cos,sin) =========
// block=128 (4 warps), 8 rows/warp. Also computes gate coefficients (block 0).
__global__ __launch_bounds__(128)
void k1_angles(const float* __restrict__ x,
               const float* __restrict__ Win,
               const float* __restrict__ bin,
               const float* __restrict__ qw)
{
    const int lane = threadIdx.x & 31;
    const int warp = threadIdx.x >> 5;
    const int row0 = (blockIdx.x * 4 + warp) * 8;

    float acc[8][8];
#pragma unroll
    for (int r = 0; r < 8; r++)
#pragma unroll
        for (int q = 0; q < NQ; q++) acc[r][q] = 0.f;

    const float4* w4 = reinterpret_cast<const float4*>(Win);
    const float4* xr[8];
#pragma unroll
    for (int r = 0; r < 8; r++)
        xr[r] = reinterpret_cast<const float4*>(x + (size_t)(row0 + r) * DIN);

#pragma unroll
    for (int j = 0; j < 8; j++) {
        float4 xv[8];
#pragma unroll
        for (int r = 0; r < 8; r++)
            xv[r] = __ldcs(&xr[r][lane + 32 * j]);
#pragma unroll
        for (int q = 0; q < NQ; q++) {
            float4 wv = __ldg(&w4[q * 256 + lane + 32 * j]);
#pragma unroll
            for (int r = 0; r < 8; r++)
                acc[r][q] += xv[r].x * wv.x + xv[r].y * wv.y
                           + xv[r].z * wv.z + xv[r].w * wv.w;
        }
    }
    // full butterfly: every lane ends with every (r,q) sum
#pragma unroll
    for (int off = 16; off; off >>= 1)
#pragma unroll
        for (int r = 0; r < 8; r++)
#pragma unroll
            for (int q = 0; q < NQ; q++)
                acc[r][q] += __shfl_xor_sync(0xffffffffu, acc[r][q], off);

    // static predicated gather: lane o = r*4 + q/2 takes (acc[r][2qh], acc[r][2qh+1])
    float h0 = acc[0][0], h1 = acc[0][1];
#pragma unroll
    for (int r = 0; r < 8; r++)
#pragma unroll
        for (int qh = 0; qh < 4; qh++) {
            const int o = r * 4 + qh;
            if (o != 0 && lane == o) { h0 = acc[r][2 * qh]; h1 = acc[r][2 * qh + 1]; }
        }

    const int rr = lane >> 2;
    const int qq = (lane & 3) * 2;
    float c0, s0, c1, s1;
    __sincosf(0.5f * (h0 + __ldg(&bin[qq])),     &s0, &c0);
    __sincosf(0.5f * (h1 + __ldg(&bin[qq + 1])), &s1, &c1);
    float4 outv = make_float4(c0, s0, c1, s1);
    *reinterpret_cast<float4*>(&g_cs[(size_t)(row0 + rr) * NQ + qq]) = outv;

    // gate-coefficient prep (one warp of block 0)
    if (blockIdx.x == 0 && threadIdx.x < NLAYERS * NQ) {
        int t = threadIdx.x;
        int l = t >> 3, i = t & 7;
        float th = qw[l * 16 + i];        // weights[l][0][i] (RX)
        float ph = qw[l * 16 + 8 + i];    // weights[l][1][i] (RZ)
        float s, c, sp, cp;
        sincosf(0.5f * th, &s, &c);
        sincosf(0.5f * ph, &sp, &cp);
        float* u = &g_ucoef[t * 8];
        u[0] =  c * cp;  u[1] = -c * sp;   // u00
        u[2] = -s * sp;  u[3] = -s * cp;   // u01
        u[4] =  s * sp;  u[5] = -s * cp;   // u10
        u[6] =  c * cp;  u[7] =  c * sp;   // u11
    }
}

// ================= K2: quantum circuit, frame-tracked (no CNOT data movement)
// One warp per row. Physical amp p = lane*8 + r; packed f32x2 pairs over r-bit0:
// reg j holds (r=2j, r=2j+1). Physical bits 7..3 = lane bits 4..0, bits 2..0 = r.
//
// Gate on logical wire t in current frame F: pair mask M = F^{-1} e_t,
// parity row R = row_t(F). CNOT(c,t) updates: g_c ^= g_t (columns), r_t ^= r_c
// (rows). All 32 (M,R) pairs and final sign rows precomputed by hand below.
template<int M, int R>
__device__ __forceinline__ void apply_gate(ull* Ar, ull* Ai,
                                           float4 ua, float4 ub, int lane)
{
    constexpr int lm    = M >> 3;        // lane shuffle mask
    constexpr int loj   = (M & 7) >> 1;  // packed-register xor
    constexpr int lo0   = M & 1;         // crosses packed pair -> swp
    constexpr int Rlane = R >> 3;
    constexpr int Rj    = (R & 7) >> 1;
    constexpr int R0    = R & 1;

    const bool pl = (__popc(lane & Rlane) & 1) != 0;

    ull o_r[4], o_i[4];
#pragma unroll
    for (int j = 0; j < 4; j++) { o_r[j] = Ar[j]; o_i[j] = Ai[j]; }

#pragma unroll
    for (int j = 0; j < 4; j++) {
        ull Pr = o_r[j ^ loj], Pi = o_i[j ^ loj];
        if (lo0) { Pr = swp(Pr); Pi = swp(Pi); }
        if (lm)  { Pr = shflx(Pr, lm); Pi = shflx(Pi, lm); }
        const bool b = pl ^ (((__popc(j & Rj)) & 1) != 0);
        ull dr, di, ndi, orr, oi, noi;
        if (R0 == 0) {
            // both packed elements share parity b
            float fdr = b ? ub.z : ua.x, fdi = b ? ub.w : ua.y;
            float foR = b ? ub.x : ua.z, foI = b ? ub.y : ua.w;
            dr = dup2(fdr); di = dup2(fdi); ndi = dup2(-fdi);
            orr = dup2(foR); oi = dup2(foI); noi = dup2(-foI);
        } else {
            // parity flips within the packed pair
            dr  = b ? pk(ub.z,  ua.x)  : pk(ua.x,  ub.z);
            di  = b ? pk(ub.w,  ua.y)  : pk(ua.y,  ub.w);
            ndi = b ? pk(-ub.w, -ua.y) : pk(-ua.y, -ub.w);
            orr = b ? pk(ub.x,  ua.z)  : pk(ua.z,  ub.x);
            oi  = b ? pk(ub.y,  ua.w)  : pk(ua.w,  ub.y);
            noi = b ? pk(-ub.y, -ua.w) : pk(-ua.w, -ub.y);
        }
        Ar[j] = fma2(noi, Pi, fma2(orr, Pr, fma2(ndi, o_i[j], mul2(dr, o_r[j]))));
        Ai[j] = fma2(oi,  Pr, fma2(orr, Pi, fma2(di,  o_r[j], mul2(dr, o_i[j]))));
    }
}

__global__ __launch_bounds__(256)
void k2_circuit()
{
    const int lane = threadIdx.x & 31;
    const int warp = threadIdx.x >> 5;
    const int row  = blockIdx.x * 8 + warp;

    float C[NQ], S[NQ];
    {
        const float4* cs4 = reinterpret_cast<const float4*>(&g_cs[(size_t)row * NQ]);
#pragma unroll
        for (int j = 0; j < 4; j++) {
            float4 v = __ldg(&cs4[j]);
            C[2 * j] = v.x; S[2 * j] = v.y; C[2 * j + 1] = v.z; S[2 * j + 1] = v.w;
        }
    }

    // initial product state (identity frame)
    float ar[8], ai[8];
    {
        float prr = 1.f, pri = 0.f;
#pragma unroll
        for (int w = 0; w < 5; w++) {
            int b = (lane >> (4 - w)) & 1;
            float qr = b ? S[w] * S[w] : C[w] * C[w];
            float qi = -S[w] * C[w];
            float nr = prr * qr - pri * qi;
            pri = prr * qi + pri * qr;
            prr = nr;
        }
#pragma unroll
        for (int r = 0; r < 8; r++) {
            float lr = prr, li = pri;
#pragma unroll
            for (int w = 5; w < 8; w++) {
                int b = (r >> (7 - w)) & 1;
                float qr = b ? S[w] * S[w] : C[w] * C[w];
                float qi = -S[w] * C[w];
                float nr = lr * qr - li * qi;
                li = lr * qi + li * qr;
                lr = nr;
            }
            ar[r] = lr; ai[r] = li;
        }
    }
    ull Ar[4], Ai[4];
#pragma unroll
    for (int j = 0; j < 4; j++) {
        Ar[j] = pk(ar[2 * j], ar[2 * j + 1]);
        Ai[j] = pk(ai[2 * j], ai[2 * j + 1]);
    }

    const float4* u4 = reinterpret_cast<const float4*>(g_ucoef);
#define G(L, I, MM, RR) { float4 ua = __ldg(&u4[((L) * 8 + (I)) * 2]); \
                          float4 ub = __ldg(&u4[((L) * 8 + (I)) * 2 + 1]); \
                          apply_gate<MM, RR>(Ar, Ai, ua, ub, lane); }
    // layer 1 (identity frame)
    G(0,0,0x80,0x80) G(0,1,0x40,0x40) G(0,2,0x20,0x20) G(0,3,0x10,0x10)
    G(0,4,0x08,0x08) G(0,5,0x04,0x04) G(0,6,0x02,0x02) G(0,7,0x01,0x01)
    // layer 2 (after CNOT chain 1)
    G(1,0,0xC0,0x80) G(1,1,0x60,0xC0) G(1,2,0x30,0xE0) G(1,3,0x18,0xF0)
    G(1,4,0x0C,0xF8) G(1,5,0x06,0xFC) G(1,6,0x03,0xFE) G(1,7,0x01,0xFF)
    // layer 3
    G(2,0,0xA0,0x80) G(2,1,0x50,0x40) G(2,2,0x28,0xA0) G(2,3,0x14,0x50)
    G(2,4,0x0A,0xA8) G(2,5,0x05,0x54) G(2,6,0x02,0xAA) G(2,7,0x01,0x55)
    // layer 4
    G(3,0,0xF0,0x80) G(3,1,0x78,0xC0) G(3,2,0x3C,0x60) G(3,3,0x1E,0x30)
    G(3,4,0x0F,0x98) G(3,5,0x07,0xCC) G(3,6,0x03,0x66) G(3,7,0x01,0x33)
#undef G

    // probabilities
    ull P[4];
#pragma unroll
    for (int j = 0; j < 4; j++) P[j] = fma2(Ai[j], Ai[j], mul2(Ar[j], Ar[j]));
    float p[8];
#pragma unroll
    for (int j = 0; j < 4; j++) up2(P[j], p[2 * j], p[2 * j + 1]);

    float ptot = ((p[0] + p[1]) + (p[2] + p[3])) + ((p[4] + p[5]) + (p[6] + p[7]));

    // final sign rows Rf = [0x80,0x40,0x20,0x10,0x88,0x44,0x22,0x11]
    float s5 = ((p[0] + p[1]) + (p[2] + p[3])) - ((p[4] + p[5]) + (p[6] + p[7]));
    float s6 = ((p[0] + p[1]) - (p[2] + p[3])) + ((p[4] + p[5]) - (p[6] + p[7]));
    float s7 = ((p[0] - p[1]) + (p[2] - p[3])) + ((p[4] - p[5]) + (p[6] - p[7]));

    float ev[NQ];
    ev[0] = (__popc(lane & 0x10) & 1) ? -ptot : ptot;
    ev[1] = (__popc(lane & 0x08) & 1) ? -ptot : ptot;
    ev[2] = (__popc(lane & 0x04) & 1) ? -ptot : ptot;
    ev[3] = (__popc(lane & 0x02) & 1) ? -ptot : ptot;
    ev[4] = (__popc(lane & 0x11) & 1) ? -ptot : ptot;
    ev[5] = (__popc(lane & 0x08) & 1) ? -s5 : s5;
    ev[6] = (__popc(lane & 0x04) & 1) ? -s6 : s6;
    ev[7] = (__popc(lane & 0x02) & 1) ? -s7 : s7;

#pragma unroll
    for (int off = 16; off; off >>= 1)
#pragma unroll
        for (int i = 0; i < NQ; i++)
            ev[i] += __shfl_xor_sync(0xffffffffu, ev[i], off);

    // static predicated gather (avoid dynamic register indexing)
    float myev = ev[0];
#pragma unroll
    for (int i = 1; i < NQ; i++)
        if (lane == i) myev = ev[i];
    if (lane < NQ)
        g_ev[(size_t)row * NQ + lane] = myev;
}

// ================= K3: out = ev @ Wout^T + bout ===========================
// 1024 blocks x 256 threads; 8 rows/block; each thread owns 4 output cols.
__global__ __launch_bounds__(256)
void k3_out(const float* __restrict__ Wout,
            const float* __restrict__ bout,
            float* __restrict__ out)
{
    const int c0   = threadIdx.x * 4;
    const int row0 = blockIdx.x * 8;

    const float4* wo4 = reinterpret_cast<const float4*>(Wout);  // [DOUT][2]
    float4 wa[4], wb[4];
#pragma unroll
    for (int k = 0; k < 4; k++) {
        wa[k] = __ldg(&wo4[(c0 + k) * 2 + 0]);
        wb[k] = __ldg(&wo4[(c0 + k) * 2 + 1]);
    }
    float4 bo = __ldg(&reinterpret_cast<const float4*>(bout)[threadIdx.x]);

#pragma unroll
    for (int r = 0; r < 8; r++) {
        int row = row0 + r;
        const float4* e4 = reinterpret_cast<const float4*>(&g_ev[(size_t)row * NQ]);
        float4 ea = __ldg(e4 + 0);
        float4 eb = __ldg(e4 + 1);
        float4 o;
        o.x = bo.x + ea.x * wa[0].x + ea.y * wa[0].y + ea.z * wa[0].z + ea.w * wa[0].w
                   + eb.x * wb[0].x + eb.y * wb[0].y + eb.z * wb[0].z + eb.w * wb[0].w;
        o.y = bo.y + ea.x * wa[1].x + ea.y * wa[1].y + ea.z * wa[1].z + ea.w * wa[1].w
                   + eb.x * wb[1].x + eb.y * wb[1].y + eb.z * wb[1].z + eb.w * wb[1].w;
        o.z = bo.z + ea.x * wa[2].x + ea.y * wa[2].y + ea.z * wa[2].z + ea.w * wa[2].w
                   + eb.x * wb[2].x + eb.y * wb[2].y + eb.z * wb[2].z + eb.w * wb[2].w;
        o.w = bo.w + ea.x * wa[3].x + ea.y * wa[3].y + ea.z * wa[3].z + ea.w * wa[3].w
                   + eb.x * wb[3].x + eb.y * wb[3].y + eb.z * wb[3].z + eb.w * wb[3].w;
        reinterpret_cast<float4*>(out + (size_t)row * DOUT)[threadIdx.x] = o;
    }
}

extern "C" void kernel_launch(void* const* d_in, const int* in_sizes, int n_in,
                              void* d_out, int out_size) {
    const float* x    = (const float*)d_in[0];
    const float* Win  = (const float*)d_in[1];
    const float* bin  = (const float*)d_in[2];
    const float* qw   = (const float*)d_in[3];
    const float* Wout = (const float*)d_in[4];
    const float* bout = (const float*)d_in[5];
    float* out = (float*)d_out;

    int B = in_sizes[0] / DIN;            // 8192
    k1_angles<<<B / 32, 128>>>(x, Win, bin, qw);
    k2_circuit<<<B / 8, 256>>>();
    k3_out<<<B / 8, 256>>>(Wout, bout, out);
}